// round 12
// baseline (speedup 1.0000x reference)
#include <cuda_runtime.h>
#include <cstdint>

#define NG     1024
#define NB     296             // blocks: one wave (148 SM x 2)
#define NT     512
#define CH4    1024            // float4 per chunk
#define CHB    16384           // bytes per array per chunk
#define ITERS  30
#define FIXF   1024.0f
#define WSHIFT 21
#define WMASK  ((1u << WSHIFT) - 1u)

typedef unsigned long long ull;

// ---------------- device scratch (no allocations allowed) ----------------
__device__ uint32_t g_part[NG * NB];
__device__ float g_alphas[NG];
__device__ int   g_any;
__device__ unsigned g_cnt0, g_flag0;
__device__ unsigned g_cnt1, g_flag1;

// ---------------- PTX helpers ----------------
__device__ __forceinline__ uint32_t s2u(const void* p) {
    return (uint32_t)__cvta_generic_to_shared(p);
}
__device__ __forceinline__ void mbar_init(uint32_t mb, uint32_t cnt) {
    asm volatile("mbarrier.init.shared.b64 [%0], %1;" :: "r"(mb), "r"(cnt) : "memory");
}
__device__ __forceinline__ void mbar_expect_tx(uint32_t mb, uint32_t bytes) {
    asm volatile("mbarrier.arrive.expect_tx.shared.b64 _, [%0], %1;" :: "r"(mb), "r"(bytes) : "memory");
}
__device__ __forceinline__ void mbar_wait(uint32_t mb, uint32_t parity) {
    uint32_t done;
    asm volatile("{\n\t.reg .pred p;\n\t"
                 "mbarrier.try_wait.parity.acquire.cta.shared::cta.b64 p, [%1], %2;\n\t"
                 "selp.b32 %0, 1, 0, p;\n\t}"
                 : "=r"(done) : "r"(mb), "r"(parity) : "memory");
    if (!done) {
        asm volatile("{\n\t.reg .pred P1;\n\t"
                     "W_%=:\n\t"
                     "mbarrier.try_wait.parity.acquire.cta.shared::cta.b64 P1, [%0], %1, 0x989680;\n\t"
                     "@P1 bra.uni D_%=;\n\t"
                     "bra.uni W_%=;\n\t"
                     "D_%=:\n\t}" :: "r"(mb), "r"(parity) : "memory");
    }
}
__device__ __forceinline__ void bulk_ld(uint32_t sdst, const void* gsrc, uint32_t bytes, uint32_t mb) {
    asm volatile("cp.async.bulk.shared::cta.global.mbarrier::complete_tx::bytes [%0], [%1], %2, [%3];"
                 :: "r"(sdst), "l"(gsrc), "r"(bytes), "r"(mb) : "memory");
}
__device__ __forceinline__ void bulk_st(void* gdst, uint32_t ssrc, uint32_t bytes) {
    asm volatile("cp.async.bulk.global.shared::cta.bulk_group [%0], [%1], %2;"
                 :: "l"(gdst), "r"(ssrc), "r"(bytes) : "memory");
}
__device__ __forceinline__ void bulk_commit() { asm volatile("cp.async.bulk.commit_group;" ::: "memory"); }
__device__ __forceinline__ void bulk_wait1()  { asm volatile("cp.async.bulk.wait_group 1;" ::: "memory"); }
__device__ __forceinline__ void bulk_wait0()  { asm volatile("cp.async.bulk.wait_group 0;" ::: "memory"); }
__device__ __forceinline__ void fence_async() { asm volatile("fence.proxy.async.shared::cta;" ::: "memory"); }

// Monotonic-generation grid barrier; all NB blocks resident (296 = 148 x 2).
__device__ __forceinline__ void grid_barrier(unsigned* cnt, unsigned* flag, int tid) {
    __syncthreads();
    if (tid == 0) {
        __threadfence();
        unsigned gen = atomicAdd(flag, 0u);
        if (atomicAdd(cnt, 1u) == NB - 1u) {
            *cnt = 0u;
            __threadfence();
            atomicAdd(flag, 1u);
        } else {
            while (atomicAdd(flag, 0u) == gen) __nanosleep(40);
        }
    }
    __syncthreads();
}

__device__ __forceinline__ void samp_one(uint32_t* acc, float a, float yr, int g) {
    float s = fminf(fmaxf(__fdividef(a, yr), 0.9f), 1.1f);
    atomicAdd(&acc[g], (1u << WSHIFT) + (uint32_t)(s * FIXF + 0.5f));
}

__device__ __forceinline__ float out_fb(float a, float b, int g) {
    float yr = fmaxf(b, 1e-9f);
    float alpha = __ldg(&g_alphas[g]);
    float v = fmaf(alpha, yr, a);
    return fminf(fmaxf(v, 0.9f * yr), 1.1f * yr);
}

__global__ void __launch_bounds__(NT) k_fused(
        const float4* __restrict__ yraw4, const float4* __restrict__ yreal4,
        const int4* __restrict__ gid4, float4* __restrict__ out4, int n4,
        const float* __restrict__ yraw, const float* __restrict__ yreal,
        const int* __restrict__ gid, float* __restrict__ out, int n) {
    extern __shared__ float4 dyn[];
    float4* s_raw  = dyn;              // [2][CH4]
    float4* s_real = dyn + 2 * CH4;    // [2][CH4]
    float4* s_out  = dyn + 4 * CH4;    // [2][CH4]
    __shared__ ull mbs[2];
    __shared__ uint32_t acc[NG];
    __shared__ float sf[NT];
    __shared__ int   s_flag;
    __shared__ float s_T;
    const int tid = threadIdx.x;
    const int bid = blockIdx.x;
    const bool samp = ((tid >> 5) & 7) == 0;     // 1 in 8 warps samples
    const int nchunks = n4 / CH4;
    const uint32_t mb0 = s2u(&mbs[0]), mb1 = s2u(&mbs[1]);

    // ====== phase 1: TMA-pipelined clip stream + sampled histogram ======
    for (int i = tid; i < NG; i += NT) acc[i] = 0u;
    if (bid == 0 && tid == 0) g_any = 0;
    if (tid == 0) { mbar_init(mb0, 1); mbar_init(mb1, 1); }
    __syncthreads();

    if (tid == 0) {                              // prologue: fill both stages
        #pragma unroll
        for (int s = 0; s < 2; s++) {
            int c = bid + s * NB;
            if (c < nchunks) {
                uint32_t mb = s ? mb1 : mb0;
                mbar_expect_tx(mb, 2 * CHB);
                bulk_ld(s2u(s_raw  + s * CH4), yraw4  + (size_t)c * CH4, CHB, mb);
                bulk_ld(s2u(s_real + s * CH4), yreal4 + (size_t)c * CH4, CHB, mb);
            }
        }
    }

    int ph0 = 0, ph1 = 0, s = 0;
    for (int c = bid; c < nchunks; c += NB, s ^= 1) {
        if (s == 0) { mbar_wait(mb0, ph0); ph0 ^= 1; }
        else        { mbar_wait(mb1, ph1); ph1 ^= 1; }
        if (tid == 0) bulk_wait1();              // out-stage s free (store c-2NB done)
        __syncthreads();

        const float4* ra = s_raw  + s * CH4;
        const float4* rb = s_real + s * CH4;
        float4*       ro = s_out  + s * CH4;
        #pragma unroll
        for (int u = 0; u < 2; u++) {
            int j = tid * 2 + u;
            float4 a = ra[j];
            float4 b = rb[j];
            float rx = fmaxf(b.x, 1e-9f), ry = fmaxf(b.y, 1e-9f);
            float rz = fmaxf(b.z, 1e-9f), rw = fmaxf(b.w, 1e-9f);
            float4 o;
            o.x = fminf(fmaxf(a.x, 0.9f * rx), 1.1f * rx);
            o.y = fminf(fmaxf(a.y, 0.9f * ry), 1.1f * ry);
            o.z = fminf(fmaxf(a.z, 0.9f * rz), 1.1f * rz);
            o.w = fminf(fmaxf(a.w, 0.9f * rw), 1.1f * rw);
            ro[j] = o;
            if (samp) {                          // warp-uniform, coalesced
                int4 g = __ldcs(&gid4[(size_t)c * CH4 + j]);
                samp_one(acc, a.x, rx, g.x);
                samp_one(acc, a.y, ry, g.y);
                samp_one(acc, a.z, rz, g.z);
                samp_one(acc, a.w, rw, g.w);
            }
        }
        __syncthreads();                         // compute done: smem stable
        if (tid == 0) {
            fence_async();                       // STS visible to async proxy
            bulk_st(out4 + (size_t)c * CH4, s2u(ro), CHB);
            bulk_commit();
            int cn = c + 2 * NB;                 // refill this stage
            if (cn < nchunks) {
                uint32_t mb = s ? mb1 : mb0;
                mbar_expect_tx(mb, 2 * CHB);
                bulk_ld(s2u(s_raw  + s * CH4), yraw4  + (size_t)cn * CH4, CHB, mb);
                bulk_ld(s2u(s_real + s * CH4), yreal4 + (size_t)cn * CH4, CHB, mb);
            }
        }
    }
    if (tid == 0) bulk_wait0();                  // flush all bulk stores

    // remainder float4s beyond nchunks*CH4, plus scalar tail
    for (int i = nchunks * CH4 + bid * NT + tid; i < n4; i += NB * NT) {
        float4 a = yraw4[i];
        float4 b = yreal4[i];
        float rx = fmaxf(b.x, 1e-9f), ry = fmaxf(b.y, 1e-9f);
        float rz = fmaxf(b.z, 1e-9f), rw = fmaxf(b.w, 1e-9f);
        float4 o;
        o.x = fminf(fmaxf(a.x, 0.9f * rx), 1.1f * rx);
        o.y = fminf(fmaxf(a.y, 0.9f * ry), 1.1f * ry);
        o.z = fminf(fmaxf(a.z, 0.9f * rz), 1.1f * rz);
        o.w = fminf(fmaxf(a.w, 0.9f * rw), 1.1f * rw);
        out4[i] = o;
    }
    {
        int t = bid * NT + tid, tb = n4 * 4;
        if (t < n - tb) {
            float a = yraw[tb + t];
            float yr = fmaxf(yreal[tb + t], 1e-9f);
            out[tb + t] = fminf(fmaxf(a, 0.9f * yr), 1.1f * yr);
        }
    }
    __syncthreads();
    for (int g = tid; g < NG; g += NT)
        g_part[g * NB + bid] = acc[g];

    grid_barrier(&g_cnt0, &g_flag0, tid);

    // ====== phase 2: sampled feasibility; exact recheck when flagged ======
    ull* accl = (ull*)sf;
    for (int g = bid; g < NG; g += NB) {
        uint32_t c = 0u, f = 0u;
        for (int b = tid; b < NB; b += NT) {
            uint32_t v = g_part[g * NB + b];
            c += v >> WSHIFT;
            f += v & WMASK;
        }
        ull v = ((ull)c << 32) | (ull)f;
        for (int o = 16; o; o >>= 1) v += __shfl_down_sync(0xffffffffu, v, o);
        if ((tid & 31) == 0) accl[tid >> 5] = v;
        __syncthreads();
        if (tid == 0) {
            ull a = 0ull;
            #pragma unroll
            for (int w = 0; w < NT / 32; w++) a += accl[w];
            int   cs = (int)(a >> 32);
            float Ss = (float)(a & 0xffffffffull) * (1.0f / FIXF);
            float m  = (cs > 0) ? Ss / (float)cs : 0.0f;
            s_flag = (cs < 32 || m < 0.96f || m > 1.04f) ? 1 : 0;
            g_alphas[g] = 0.0f;
        }
        __syncthreads();
        if (!s_flag) continue;

        // exact recheck: full scan for n_g and S0
        float s0 = 0.0f, cg = 0.0f;
        for (int i = tid; i < n; i += NT) {
            if (gid[i] == g) {
                float yr = fmaxf(yreal[i], 1e-9f);
                s0 += fminf(fmaxf(yraw[i] / yr, 0.9f), 1.1f);
                cg += 1.0f;
            }
        }
        sf[tid] = s0; __syncthreads();
        for (int d = NT / 2; d > 0; d >>= 1) { if (tid < d) sf[tid] += sf[tid + d]; __syncthreads(); }
        s0 = sf[0]; __syncthreads();
        sf[tid] = cg; __syncthreads();
        for (int d = NT / 2; d > 0; d >>= 1) { if (tid < d) sf[tid] += sf[tid + d]; __syncthreads(); }
        cg = sf[0]; __syncthreads();

        float L = 0.95f * cg, U = 1.05f * cg;
        bool infeas = (cg > 0.0f) && (s0 < L || s0 > U);
        if (tid == 0) {
            s_T = (s0 < L) ? L : U;
            if (infeas) atomicExch(&g_any, 1);
            s_flag = infeas ? 1 : 0;
        }
        __syncthreads();
        if (!s_flag) continue;

        // exact bisection fallback
        float rmn = __int_as_float(0x7f800000);
        float rmx = __int_as_float(0xff800000);
        for (int i = tid; i < n; i += NT) {
            if (gid[i] == g) {
                float yr = fmaxf(yreal[i], 1e-9f);
                float r  = yraw[i] / yr;
                rmn = fminf(rmn, r);
                rmx = fmaxf(rmx, r);
            }
        }
        sf[tid] = rmn; __syncthreads();
        for (int d = NT / 2; d > 0; d >>= 1) { if (tid < d) sf[tid] = fminf(sf[tid], sf[tid + d]); __syncthreads(); }
        rmn = sf[0]; __syncthreads();
        sf[tid] = rmx; __syncthreads();
        for (int d = NT / 2; d > 0; d >>= 1) { if (tid < d) sf[tid] = fmaxf(sf[tid], sf[tid + d]); __syncthreads(); }
        rmx = sf[0]; __syncthreads();

        float lo = 0.9f - rmx - 1.0f;
        float hi = 1.1f - rmn + 1.0f;
        float T = s_T;
        float mid = lo;
        for (int it = 0; it < ITERS; ++it) {
            mid = 0.5f * (lo + hi);
            float p = 0.0f;
            for (int i = tid; i < n; i += NT) {
                if (gid[i] == g) {
                    float yr = fmaxf(yreal[i], 1e-9f);
                    float r  = yraw[i] / yr;
                    p += fminf(fmaxf(r + mid, 0.9f), 1.1f);
                }
            }
            sf[tid] = p; __syncthreads();
            for (int d = NT / 2; d > 0; d >>= 1) { if (tid < d) sf[tid] += sf[tid + d]; __syncthreads(); }
            float S2 = sf[0]; __syncthreads();
            if (S2 < T) lo = mid; else hi = mid;
        }
        if (tid == 0) g_alphas[g] = mid;
        __syncthreads();
    }

    grid_barrier(&g_cnt1, &g_flag1, tid);

    // ====== phase 3: rewrite pass — ONLY if some group truly infeasible ======
    if (g_any) {
        const int stride = NB * NT;
        for (int i = bid * NT + tid; i < n4; i += stride) {
            float4 a = yraw4[i];
            float4 b = yreal4[i];
            int4   g = gid4[i];
            float4 o;
            o.x = out_fb(a.x, b.x, g.x);
            o.y = out_fb(a.y, b.y, g.y);
            o.z = out_fb(a.z, b.z, g.z);
            o.w = out_fb(a.w, b.w, g.w);
            out4[i] = o;
        }
        int t = bid * NT + tid, tb = n4 * 4;
        if (t < n - tb) out[tb + t] = out_fb(yraw[tb + t], yreal[tb + t], gid[tb + t]);
    }
}

// ---------------- launch ----------------
extern "C" void kernel_launch(void* const* d_in, const int* in_sizes, int n_in,
                              void* d_out, int out_size) {
    const float* yraw  = (const float*)d_in[0];
    const float* yreal = (const float*)d_in[1];
    const int*   gid   = (const int*)d_in[2];
    float* out = (float*)d_out;
    int n  = in_sizes[0];
    int n4 = n >> 2;

    const int dyn = 6 * CH4 * (int)sizeof(float4);   // 96KB
    static int configured = 0;
    if (!configured) {
        cudaFuncSetAttribute(k_fused, cudaFuncAttributeMaxDynamicSharedMemorySize, dyn);
        configured = 1;
    }
    k_fused<<<NB, NT, dyn>>>((const float4*)yraw, (const float4*)yreal, (const int4*)gid,
                             (float4*)d_out, n4, yraw, yreal, gid, out, n);
}

// round 13
// speedup vs baseline: 1.1503x; 1.1503x over previous
#include <cuda_runtime.h>
#include <cstdint>

#define NG     1024
#define NB     444             // blocks: one wave (148 SM x 3)
#define NT     512
#define ITERS  30
#define FIXF   1024.0f
#define WSHIFT 21
#define WMASK  ((1u << WSHIFT) - 1u)

typedef unsigned long long ull;

// ---------------- device scratch (no allocations allowed) ----------------
__device__ uint32_t g_part[NG * NB];
__device__ float g_alphas[NG];
__device__ int   g_any;
__device__ unsigned g_cnt0, g_flag0;
__device__ unsigned g_cnt1, g_flag1;

// Monotonic-generation grid barrier; all NB blocks resident (444 = 148 x 3;
// 6KB static smem, 42 regs @ 512 thr x 3 blocks = ok).
__device__ __forceinline__ void grid_barrier(unsigned* cnt, unsigned* flag, int tid) {
    __syncthreads();
    if (tid == 0) {
        __threadfence();
        unsigned gen = atomicAdd(flag, 0u);
        if (atomicAdd(cnt, 1u) == NB - 1u) {
            *cnt = 0u;
            __threadfence();
            atomicAdd(flag, 1u);
        } else {
            while (atomicAdd(flag, 0u) == gen) __nanosleep(40);
        }
    }
    __syncthreads();
}

__device__ __forceinline__ void samp_one(uint32_t* acc, float a, float yr, int g) {
    float s = fminf(fmaxf(__fdividef(a, yr), 0.9f), 1.1f);
    atomicAdd(&acc[g], (1u << WSHIFT) + (uint32_t)(s * FIXF + 0.5f));
}

__device__ __forceinline__ float4 clip4(float4 a, float4 b) {
    float rx = fmaxf(b.x, 1e-9f), ry = fmaxf(b.y, 1e-9f);
    float rz = fmaxf(b.z, 1e-9f), rw = fmaxf(b.w, 1e-9f);
    float4 o;
    o.x = fminf(fmaxf(a.x, 0.9f * rx), 1.1f * rx);
    o.y = fminf(fmaxf(a.y, 0.9f * ry), 1.1f * ry);
    o.z = fminf(fmaxf(a.z, 0.9f * rz), 1.1f * rz);
    o.w = fminf(fmaxf(a.w, 0.9f * rw), 1.1f * rw);
    return o;
}

__device__ __forceinline__ void samp4(uint32_t* acc, float4 a, float4 b, int4 g) {
    samp_one(acc, a.x, fmaxf(b.x, 1e-9f), g.x);
    samp_one(acc, a.y, fmaxf(b.y, 1e-9f), g.y);
    samp_one(acc, a.z, fmaxf(b.z, 1e-9f), g.z);
    samp_one(acc, a.w, fmaxf(b.w, 1e-9f), g.w);
}

__device__ __forceinline__ float out_fb(float a, float b, int g) {
    float yr = fmaxf(b, 1e-9f);
    float alpha = __ldg(&g_alphas[g]);
    float v = fmaf(alpha, yr, a);
    return fminf(fmaxf(v, 0.9f * yr), 1.1f * yr);
}

__global__ void __launch_bounds__(NT, 3) k_fused(
        const float4* __restrict__ yraw4, const float4* __restrict__ yreal4,
        const int4* __restrict__ gid4, float4* __restrict__ out4, int n4,
        const float* __restrict__ yraw, const float* __restrict__ yreal,
        const int* __restrict__ gid, float* __restrict__ out, int n) {
    __shared__ uint32_t acc[NG];
    __shared__ float sf[NT];
    __shared__ int   s_flag;
    __shared__ float s_T;
    const int tid = threadIdx.x;
    const int bid = blockIdx.x;
    const bool samp = ((tid >> 5) & 7) == 0;      // 1 in 8 warps samples
    const int stride = NB * 2 * NT;               // 2 float4 per thread per iter

    // ====== phase 1: 2-wide ILP clip stream + sampled histogram ======
    for (int i = tid; i < NG; i += NT) acc[i] = 0u;
    if (bid == 0 && tid == 0) g_any = 0;
    __syncthreads();

    int i0 = bid * 2 * NT + tid;
    for (; i0 + NT < n4; i0 += stride) {
        int i1 = i0 + NT;
        // front-batched independent loads (4x LDG.128 + sampled 2x LDG.128)
        float4 a0 = __ldcs(&yraw4[i0]);
        float4 a1 = __ldcs(&yraw4[i1]);
        float4 b0 = __ldcs(&yreal4[i0]);
        float4 b1 = __ldcs(&yreal4[i1]);
        __stcs(&out4[i0], clip4(a0, b0));
        __stcs(&out4[i1], clip4(a1, b1));
        if (samp) {                               // warp-uniform, coalesced
            int4 g0 = __ldcs(&gid4[i0]);
            int4 g1 = __ldcs(&gid4[i1]);
            samp4(acc, a0, b0, g0);
            samp4(acc, a1, b1, g1);
        }
    }
    // residual float4s (one at a time)
    for (; i0 < n4; i0 += NT) {                   // at most covers the partial pair
        float4 a = __ldcs(&yraw4[i0]);
        float4 b = __ldcs(&yreal4[i0]);
        __stcs(&out4[i0], clip4(a, b));
        if (samp) {
            int4 g = __ldcs(&gid4[i0]);
            samp4(acc, a, b, g);
        }
    }
    {   // scalar tail (n not multiple of 4)
        int t = bid * NT + tid, tb = n4 * 4;
        if (t < n - tb) {
            float a = yraw[tb + t];
            float yr = fmaxf(yreal[tb + t], 1e-9f);
            out[tb + t] = fminf(fmaxf(a, 0.9f * yr), 1.1f * yr);
        }
    }
    __syncthreads();
    for (int g = tid; g < NG; g += NT)
        g_part[g * NB + bid] = acc[g];

    grid_barrier(&g_cnt0, &g_flag0, tid);

    // ====== phase 2: sampled feasibility; exact recheck when flagged ======
    ull* accl = (ull*)sf;
    for (int g = bid; g < NG; g += NB) {
        uint32_t c = 0u, f = 0u;
        for (int b = tid; b < NB; b += NT) {
            uint32_t v = g_part[g * NB + b];
            c += v >> WSHIFT;
            f += v & WMASK;
        }
        ull v = ((ull)c << 32) | (ull)f;
        for (int o = 16; o; o >>= 1) v += __shfl_down_sync(0xffffffffu, v, o);
        if ((tid & 31) == 0) accl[tid >> 5] = v;
        __syncthreads();
        if (tid == 0) {
            ull a = 0ull;
            #pragma unroll
            for (int w = 0; w < NT / 32; w++) a += accl[w];
            int   cs = (int)(a >> 32);
            float Ss = (float)(a & 0xffffffffull) * (1.0f / FIXF);
            float m  = (cs > 0) ? Ss / (float)cs : 0.0f;
            s_flag = (cs < 32 || m < 0.96f || m > 1.04f) ? 1 : 0;
            g_alphas[g] = 0.0f;
        }
        __syncthreads();
        if (!s_flag) continue;                    // sampled fast path

        // exact recheck: full scan for n_g and S0
        float s0 = 0.0f, cg = 0.0f;
        for (int i = tid; i < n; i += NT) {
            if (gid[i] == g) {
                float yr = fmaxf(yreal[i], 1e-9f);
                s0 += fminf(fmaxf(yraw[i] / yr, 0.9f), 1.1f);
                cg += 1.0f;
            }
        }
        sf[tid] = s0; __syncthreads();
        for (int d = NT / 2; d > 0; d >>= 1) { if (tid < d) sf[tid] += sf[tid + d]; __syncthreads(); }
        s0 = sf[0]; __syncthreads();
        sf[tid] = cg; __syncthreads();
        for (int d = NT / 2; d > 0; d >>= 1) { if (tid < d) sf[tid] += sf[tid + d]; __syncthreads(); }
        cg = sf[0]; __syncthreads();

        float L = 0.95f * cg, U = 1.05f * cg;
        bool infeas = (cg > 0.0f) && (s0 < L || s0 > U);
        if (tid == 0) {
            s_T = (s0 < L) ? L : U;
            if (infeas) atomicExch(&g_any, 1);
            s_flag = infeas ? 1 : 0;
        }
        __syncthreads();
        if (!s_flag) continue;                    // exactly feasible

        // exact bisection fallback
        float rmn = __int_as_float(0x7f800000);
        float rmx = __int_as_float(0xff800000);
        for (int i = tid; i < n; i += NT) {
            if (gid[i] == g) {
                float yr = fmaxf(yreal[i], 1e-9f);
                float r  = yraw[i] / yr;
                rmn = fminf(rmn, r);
                rmx = fmaxf(rmx, r);
            }
        }
        sf[tid] = rmn; __syncthreads();
        for (int d = NT / 2; d > 0; d >>= 1) { if (tid < d) sf[tid] = fminf(sf[tid], sf[tid + d]); __syncthreads(); }
        rmn = sf[0]; __syncthreads();
        sf[tid] = rmx; __syncthreads();
        for (int d = NT / 2; d > 0; d >>= 1) { if (tid < d) sf[tid] = fmaxf(sf[tid], sf[tid + d]); __syncthreads(); }
        rmx = sf[0]; __syncthreads();

        float lo = 0.9f - rmx - 1.0f;
        float hi = 1.1f - rmn + 1.0f;
        float T = s_T;
        float mid = lo;
        for (int it = 0; it < ITERS; ++it) {
            mid = 0.5f * (lo + hi);
            float p = 0.0f;
            for (int i = tid; i < n; i += NT) {
                if (gid[i] == g) {
                    float yr = fmaxf(yreal[i], 1e-9f);
                    float r  = yraw[i] / yr;
                    p += fminf(fmaxf(r + mid, 0.9f), 1.1f);
                }
            }
            sf[tid] = p; __syncthreads();
            for (int d = NT / 2; d > 0; d >>= 1) { if (tid < d) sf[tid] += sf[tid + d]; __syncthreads(); }
            float S2 = sf[0]; __syncthreads();
            if (S2 < T) lo = mid; else hi = mid;
        }
        if (tid == 0) g_alphas[g] = mid;
        __syncthreads();
    }

    grid_barrier(&g_cnt1, &g_flag1, tid);

    // ====== phase 3: rewrite pass — ONLY if some group truly infeasible ======
    if (g_any) {
        const int st = NB * NT;
        for (int i = bid * NT + tid; i < n4; i += st) {
            float4 a = yraw4[i];
            float4 b = yreal4[i];
            int4   g = gid4[i];
            float4 o;
            o.x = out_fb(a.x, b.x, g.x);
            o.y = out_fb(a.y, b.y, g.y);
            o.z = out_fb(a.z, b.z, g.z);
            o.w = out_fb(a.w, b.w, g.w);
            out4[i] = o;
        }
        int t = bid * NT + tid, tb = n4 * 4;
        if (t < n - tb) out[tb + t] = out_fb(yraw[tb + t], yreal[tb + t], gid[tb + t]);
    }
}

// ---------------- launch ----------------
extern "C" void kernel_launch(void* const* d_in, const int* in_sizes, int n_in,
                              void* d_out, int out_size) {
    const float* yraw  = (const float*)d_in[0];
    const float* yreal = (const float*)d_in[1];
    const int*   gid   = (const int*)d_in[2];
    float* out = (float*)d_out;
    int n  = in_sizes[0];
    int n4 = n >> 2;

    k_fused<<<NB, NT>>>((const float4*)yraw, (const float4*)yreal, (const int4*)gid,
                        (float4*)d_out, n4, yraw, yreal, gid, out, n);
}

// round 14
// speedup vs baseline: 1.2531x; 1.0894x over previous
#include <cuda_runtime.h>
#include <cstdint>

#define NG     1024
#define NB     444             // blocks: one wave (148 SM x 3)
#define NT     512
#define ITERS  30
#define FIXF   1024.0f
#define WSHIFT 21
#define WMASK  ((1u << WSHIFT) - 1u)

typedef unsigned long long ull;

// ---------------- device scratch (no allocations allowed) ----------------
__device__ uint32_t g_part[NG * NB];
__device__ float g_alphas[NG];
__device__ int   g_any;
__device__ unsigned g_cnt0, g_flag0;
__device__ unsigned g_cnt1, g_flag1;

// Monotonic-generation grid barrier; all NB blocks resident (444 = 148 x 3).
__device__ __forceinline__ void grid_barrier(unsigned* cnt, unsigned* flag, int tid) {
    __syncthreads();
    if (tid == 0) {
        __threadfence();
        unsigned gen = atomicAdd(flag, 0u);
        if (atomicAdd(cnt, 1u) == NB - 1u) {
            *cnt = 0u;
            __threadfence();
            atomicAdd(flag, 1u);
        } else {
            while (atomicAdd(flag, 0u) == gen) __nanosleep(40);
        }
    }
    __syncthreads();
}

__device__ __forceinline__ void samp_one(uint32_t* acc, float a, float yr, int g) {
    float s = fminf(fmaxf(__fdividef(a, yr), 0.9f), 1.1f);
    atomicAdd(&acc[g], (1u << WSHIFT) + (uint32_t)(s * FIXF + 0.5f));
}

__device__ __forceinline__ float4 clip4(float4 a, float4 b) {
    float rx = fmaxf(b.x, 1e-9f), ry = fmaxf(b.y, 1e-9f);
    float rz = fmaxf(b.z, 1e-9f), rw = fmaxf(b.w, 1e-9f);
    float4 o;
    o.x = fminf(fmaxf(a.x, 0.9f * rx), 1.1f * rx);
    o.y = fminf(fmaxf(a.y, 0.9f * ry), 1.1f * ry);
    o.z = fminf(fmaxf(a.z, 0.9f * rz), 1.1f * rz);
    o.w = fminf(fmaxf(a.w, 0.9f * rw), 1.1f * rw);
    return o;
}

__device__ __forceinline__ void samp4(uint32_t* acc, float4 a, float4 b, int4 g) {
    samp_one(acc, a.x, fmaxf(b.x, 1e-9f), g.x);
    samp_one(acc, a.y, fmaxf(b.y, 1e-9f), g.y);
    samp_one(acc, a.z, fmaxf(b.z, 1e-9f), g.z);
    samp_one(acc, a.w, fmaxf(b.w, 1e-9f), g.w);
}

__device__ __forceinline__ float out_fb(float a, float b, int g) {
    float yr = fmaxf(b, 1e-9f);
    float alpha = __ldg(&g_alphas[g]);
    float v = fmaf(alpha, yr, a);
    return fminf(fmaxf(v, 0.9f * yr), 1.1f * yr);
}

__global__ void __launch_bounds__(NT, 3) k_fused(
        const float4* __restrict__ yraw4, const float4* __restrict__ yreal4,
        const int4* __restrict__ gid4, float4* __restrict__ out4, int n4,
        const float* __restrict__ yraw, const float* __restrict__ yreal,
        const int* __restrict__ gid, float* __restrict__ out, int n) {
    __shared__ uint32_t acc[NG];
    __shared__ float sf[NT];
    __shared__ int   s_flag;
    __shared__ float s_T;
    const int tid = threadIdx.x;
    const int bid = blockIdx.x;
    const int wsel = (tid >> 5) & 7;              // this warp's sampling slot
    const int stride = NB * 2 * NT;               // 2 float4 per thread per iter

    // ====== phase 1: balanced temporal-sampled clip stream ======
    for (int i = tid; i < NG; i += NT) acc[i] = 0u;
    if (bid == 0 && tid == 0) g_any = 0;
    __syncthreads();

    int i0 = bid * 2 * NT + tid;
    int k = 0;
    for (; i0 + NT < n4; i0 += stride, k++) {
        int i1 = i0 + NT;
        float4 a0 = __ldcs(&yraw4[i0]);
        float4 a1 = __ldcs(&yraw4[i1]);
        float4 b0 = __ldcs(&yreal4[i0]);
        float4 b1 = __ldcs(&yreal4[i1]);
        __stcs(&out4[i0], clip4(a0, b0));
        __stcs(&out4[i1], clip4(a1, b1));
        if (((k ^ wsel) & 7) == 0) {              // every warp, 1/8 of its iters
            int4 g0 = __ldcs(&gid4[i0]);
            int4 g1 = __ldcs(&gid4[i1]);
            samp4(acc, a0, b0, g0);
            samp4(acc, a1, b1, g1);
        }
    }
    // residual float4s
    for (; i0 < n4; i0 += NT) {
        float4 a = __ldcs(&yraw4[i0]);
        float4 b = __ldcs(&yreal4[i0]);
        __stcs(&out4[i0], clip4(a, b));
        if (((k ^ wsel) & 7) == 0) {
            int4 g = __ldcs(&gid4[i0]);
            samp4(acc, a, b, g);
        }
    }
    {   // scalar tail (n not multiple of 4)
        int t = bid * NT + tid, tb = n4 * 4;
        if (t < n - tb) {
            float a = yraw[tb + t];
            float yr = fmaxf(yreal[tb + t], 1e-9f);
            out[tb + t] = fminf(fmaxf(a, 0.9f * yr), 1.1f * yr);
        }
    }
    __syncthreads();
    for (int g = tid; g < NG; g += NT)
        g_part[g * NB + bid] = acc[g];

    grid_barrier(&g_cnt0, &g_flag0, tid);

    // ====== phase 2: sampled feasibility; exact recheck when flagged ======
    ull* accl = (ull*)sf;
    for (int g = bid; g < NG; g += NB) {
        uint32_t c = 0u, f = 0u;
        for (int b = tid; b < NB; b += NT) {
            uint32_t v = g_part[g * NB + b];
            c += v >> WSHIFT;
            f += v & WMASK;
        }
        ull v = ((ull)c << 32) | (ull)f;
        for (int o = 16; o; o >>= 1) v += __shfl_down_sync(0xffffffffu, v, o);
        if ((tid & 31) == 0) accl[tid >> 5] = v;
        __syncthreads();
        if (tid == 0) {
            ull a = 0ull;
            #pragma unroll
            for (int w = 0; w < NT / 32; w++) a += accl[w];
            int   cs = (int)(a >> 32);
            float Ss = (float)(a & 0xffffffffull) * (1.0f / FIXF);
            float m  = (cs > 0) ? Ss / (float)cs : 0.0f;
            s_flag = (cs < 32 || m < 0.96f || m > 1.04f) ? 1 : 0;
            g_alphas[g] = 0.0f;
        }
        __syncthreads();
        if (!s_flag) continue;                    // sampled fast path

        // exact recheck: full scan for n_g and S0
        float s0 = 0.0f, cg = 0.0f;
        for (int i = tid; i < n; i += NT) {
            if (gid[i] == g) {
                float yr = fmaxf(yreal[i], 1e-9f);
                s0 += fminf(fmaxf(yraw[i] / yr, 0.9f), 1.1f);
                cg += 1.0f;
            }
        }
        sf[tid] = s0; __syncthreads();
        for (int d = NT / 2; d > 0; d >>= 1) { if (tid < d) sf[tid] += sf[tid + d]; __syncthreads(); }
        s0 = sf[0]; __syncthreads();
        sf[tid] = cg; __syncthreads();
        for (int d = NT / 2; d > 0; d >>= 1) { if (tid < d) sf[tid] += sf[tid + d]; __syncthreads(); }
        cg = sf[0]; __syncthreads();

        float L = 0.95f * cg, U = 1.05f * cg;
        bool infeas = (cg > 0.0f) && (s0 < L || s0 > U);
        if (tid == 0) {
            s_T = (s0 < L) ? L : U;
            if (infeas) atomicExch(&g_any, 1);
            s_flag = infeas ? 1 : 0;
        }
        __syncthreads();
        if (!s_flag) continue;                    // exactly feasible

        // exact bisection fallback
        float rmn = __int_as_float(0x7f800000);
        float rmx = __int_as_float(0xff800000);
        for (int i = tid; i < n; i += NT) {
            if (gid[i] == g) {
                float yr = fmaxf(yreal[i], 1e-9f);
                float r  = yraw[i] / yr;
                rmn = fminf(rmn, r);
                rmx = fmaxf(rmx, r);
            }
        }
        sf[tid] = rmn; __syncthreads();
        for (int d = NT / 2; d > 0; d >>= 1) { if (tid < d) sf[tid] = fminf(sf[tid], sf[tid + d]); __syncthreads(); }
        rmn = sf[0]; __syncthreads();
        sf[tid] = rmx; __syncthreads();
        for (int d = NT / 2; d > 0; d >>= 1) { if (tid < d) sf[tid] = fmaxf(sf[tid], sf[tid + d]); __syncthreads(); }
        rmx = sf[0]; __syncthreads();

        float lo = 0.9f - rmx - 1.0f;
        float hi = 1.1f - rmn + 1.0f;
        float T = s_T;
        float mid = lo;
        for (int it = 0; it < ITERS; ++it) {
            mid = 0.5f * (lo + hi);
            float p = 0.0f;
            for (int i = tid; i < n; i += NT) {
                if (gid[i] == g) {
                    float yr = fmaxf(yreal[i], 1e-9f);
                    float r  = yraw[i] / yr;
                    p += fminf(fmaxf(r + mid, 0.9f), 1.1f);
                }
            }
            sf[tid] = p; __syncthreads();
            for (int d = NT / 2; d > 0; d >>= 1) { if (tid < d) sf[tid] += sf[tid + d]; __syncthreads(); }
            float S2 = sf[0]; __syncthreads();
            if (S2 < T) lo = mid; else hi = mid;
        }
        if (tid == 0) g_alphas[g] = mid;
        __syncthreads();
    }

    grid_barrier(&g_cnt1, &g_flag1, tid);

    // ====== phase 3: rewrite pass — ONLY if some group truly infeasible ======
    if (g_any) {
        const int st = NB * NT;
        for (int i = bid * NT + tid; i < n4; i += st) {
            float4 a = yraw4[i];
            float4 b = yreal4[i];
            int4   g = gid4[i];
            float4 o;
            o.x = out_fb(a.x, b.x, g.x);
            o.y = out_fb(a.y, b.y, g.y);
            o.z = out_fb(a.z, b.z, g.z);
            o.w = out_fb(a.w, b.w, g.w);
            out4[i] = o;
        }
        int t = bid * NT + tid, tb = n4 * 4;
        if (t < n - tb) out[tb + t] = out_fb(yraw[tb + t], yreal[tb + t], gid[tb + t]);
    }
}

// ---------------- launch ----------------
extern "C" void kernel_launch(void* const* d_in, const int* in_sizes, int n_in,
                              void* d_out, int out_size) {
    const float* yraw  = (const float*)d_in[0];
    const float* yreal = (const float*)d_in[1];
    const int*   gid   = (const int*)d_in[2];
    float* out = (float*)d_out;
    int n  = in_sizes[0];
    int n4 = n >> 2;

    k_fused<<<NB, NT>>>((const float4*)yraw, (const float4*)yreal, (const int4*)gid,
                        (float4*)d_out, n4, yraw, yreal, gid, out, n);
}